// round 16
// baseline (speedup 1.0000x reference)
#include <cuda_runtime.h>
#include <cuda_bf16.h>
#include <cstdint>

// LSTM decoder: B=1024, H=128, O=7, T=512.
// gates = h @ (W_ih+W_hh)^T + (b_ih+b_hh)
// Grid = 148 blocks (136 x 7 rows + 12 x 6 rows). TPB=256 (2 warps/SMSP).
// K-SPLIT + SCALAR FFMA: thread (u = t&127, kh = t>>7) accumulates all NR
// rows over its 64-k half with scalar fp32 FMA (tests FFMA rt1: 2 warps/SMSP
// doubles issue coverage while per-warp weight-LDS halves vs row-split).
// Partials exchanged via SMEM; elementwise split by k-half; 2 syncs/step.
// o-gate depth-8 ring prefetch from L2; pred GEMM in prologue LDG shadow;
// fused sig*tanh MUFU (8 MUFU/row).

#define B_TOTAL   1024
#define HID       128
#define GATES     512
#define T_STEPS   512
#define OUT_DIM   7
#define RMAX      7
#define NBLOCKS   148
#define NB7       136               // blocks with 7 rows (136*7 + 12*6 = 1024)
#define TPB       256

__device__ float4 g_W[32 * GATES];   // [k4][g] combined transposed weights, 256 KB
__device__ float  g_bias[GATES];

// ---------- helpers ----------
__device__ __forceinline__ float sigf(float x) {
    return __fdividef(1.0f, 1.0f + __expf(-x));
}
// sig(a)*tanh(b) = (1 - e^{-2b}) / ((1 + e^{-a}) (1 + e^{-2b}))  : 2 EX2 + 1 RCP
__device__ __forceinline__ float sig_mul_tanh(float a, float b) {
    float ea = __expf(-a);
    float eb = __expf(-2.0f * b);
    return __fdividef(1.0f - eb, (1.0f + ea) * (1.0f + eb));
}
__device__ __forceinline__ void fma4(float& acc, float4 h, float4 w) {
    acc = fmaf(h.x, w.x, acc);
    acc = fmaf(h.y, w.y, acc);
    acc = fmaf(h.z, w.z, acc);
    acc = fmaf(h.w, w.w, acc);
}

// ---------- prep ----------
__global__ void prep_kernel(const float* __restrict__ Wih,
                            const float* __restrict__ Whh,
                            const float* __restrict__ bih,
                            const float* __restrict__ bhh) {
    int idx = blockIdx.x * blockDim.x + threadIdx.x;
    if (idx < 32 * GATES) {
        int g  = idx & (GATES - 1);
        int k4 = idx >> 9;
        int base = g * HID + k4 * 4;
        float4 v;
        v.x = Wih[base + 0] + Whh[base + 0];
        v.y = Wih[base + 1] + Whh[base + 1];
        v.z = Wih[base + 2] + Whh[base + 2];
        v.w = Wih[base + 3] + Whh[base + 3];
        g_W[k4 * GATES + g] = v;
    }
    if (idx < GATES) g_bias[idx] = bih[idx] + bhh[idx];
}

// ---------- SMEM layout (floats) ----------
#define SW_F4       (32 * 384)                     // 12288 float4 : gates i,f,g (192 KB)
#define SH_OFF_F    (SW_F4 * 4)                    // 49152 : h double buffer 2*RMAX*128
#define SEX_OFF_F   (SH_OFF_F + 2 * RMAX * HID)    // 50944 : float4[RMAX][128] partials
#define SWOUT_OFF_F (SEX_OFF_F + RMAX * HID * 4)   // 54528 : float4[7][33]
#define SMEM_BYTES  ((SWOUT_OFF_F + OUT_DIM * 33 * 4) * 4)   // 221808

template<int NR>
__device__ __forceinline__ void lstm_body(const float* __restrict__ ctx,
                                          const float* __restrict__ Wout,
                                          const float* __restrict__ bout,
                                          float* __restrict__ out,
                                          int row_base) {
    constexpr int R0c = (NR + 1) / 2;   // rows owned by kh=0
    constexpr int R1c = NR - R0c;       // rows owned by kh=1

    extern __shared__ float smem[];
    float4* s_w    = reinterpret_cast<float4*>(smem);
    float*  s_h    = smem + SH_OFF_F;
    float4* s_ex   = reinterpret_cast<float4*>(smem + SEX_OFF_F);   // [row][u]
    float4* s_wout = reinterpret_cast<float4*>(smem + SWOUT_OFF_F);

    const int t  = threadIdx.x;
    const int u  = t & (HID - 1);    // hidden unit
    const int kh = t >> 7;           // k-half: 0 -> k4 0..15, 1 -> k4 16..31
    const int kb = kh * 16;          // k4 base

    // stage W (i,f,g) into shared
    for (int i = t; i < SW_F4; i += TPB) {
        int k4 = i / 384;
        int g  = i - k4 * 384;
        s_w[i] = g_W[k4 * GATES + g];
    }
    // stage W_out (padded pitch 33)
    const float4* Wout4 = reinterpret_cast<const float4*>(Wout);
    for (int i = t; i < OUT_DIM * 32; i += TPB) {
        int o = i / 32, kk = i - o * 32;
        s_wout[o * 33 + kk] = Wout4[o * 32 + kk];
    }
    // h0 = ctx[b][255][:]
    for (int i = t; i < NR * HID; i += TPB) {
        int r = i >> 7, col = i & (HID - 1);
        int b = row_base + r;
        s_h[r * HID + col] = ctx[((size_t)b * 256 + 255) * HID + col];
    }

    // biases folded into kh=0's accumulator init only
    const float bi = (kh == 0) ? g_bias[u]           : 0.0f;
    const float bf = (kh == 0) ? g_bias[HID + u]     : 0.0f;
    const float bg = (kh == 0) ? g_bias[2 * HID + u] : 0.0f;
    const float bo = (kh == 0) ? g_bias[3 * HID + u] : 0.0f;

    // o-gate L2 stream base (row pitch GATES float4 per k4)
    const float4* __restrict__ wO = &g_W[3 * HID + u];

    // pred mapping: warp pr owns row pr (if < NR), 7 active lanes per warp
    const int pr = t >> 5;          // 0..7
    const int po = t & 31;
    const bool do_pred = (po < OUT_DIM) && (pr < NR);
    const float bpred = do_pred ? bout[po] : 0.0f;
    float* out_base = out + ((size_t)(row_base + pr) * T_STEPS) * OUT_DIM + po;

    float c[R0c];                    // kh=0: rows 0..R0c-1 ; kh=1: rows R0c..NR-1
#pragma unroll
    for (int r = 0; r < R0c; r++) c[r] = 0.0f;

    __syncthreads();

    int cur = 0;
    for (int s = 0; s < T_STEPS; s++) {
        const float* hc = s_h + cur * (RMAX * HID);
        float*       hn = s_h + (cur ^ 1) * (RMAX * HID);

        // ---- deep o-gate prefetch (8 LDGs in flight, this k-half) ----
        float4 w3buf[8];
#pragma unroll
        for (int j = 0; j < 8; j++) w3buf[j] = __ldg(&wO[(size_t)(kb + j) * GATES]);

        // ---- pred for step s-1 in the LDG latency shadow ----
        if (s > 0 && do_pred) {
            const float4* hr = reinterpret_cast<const float4*>(hc + pr * HID);
            const float4* wr = s_wout + po * 33;
            float pa = 0.0f;
#pragma unroll 8
            for (int kk = 0; kk < 32; kk++) {
                float4 hv = hr[kk];
                float4 wv = wr[kk];
                pa += hv.x * wv.x + hv.y * wv.y + hv.z * wv.z + hv.w * wv.w;
            }
            out_base[(size_t)(s - 1) * OUT_DIM] = pa + bpred;
        }

        // scalar accumulators: one fp32 per (gate,row)
        float a0[NR], a1[NR], a2[NR], a3[NR];
#pragma unroll
        for (int r = 0; r < NR; r++) { a0[r] = bi; a1[r] = bf; a2[r] = bg; a3[r] = bo; }

#pragma unroll 8
        for (int kq = 0; kq < 16; kq++) {
            const int k4 = kb + kq;
            float4 w0 = s_w[k4 * 384 + u];
            float4 w1 = s_w[k4 * 384 + HID + u];
            float4 w2 = s_w[k4 * 384 + 2 * HID + u];
            float4 w3 = w3buf[kq & 7];
            if (kq + 8 < 16)
                w3buf[kq & 7] = __ldg(&wO[(size_t)(k4 + 8) * GATES]);
#pragma unroll
            for (int r = 0; r < NR; r++) {
                float4 h4 = *reinterpret_cast<const float4*>(hc + r * HID + k4 * 4); // bcast
                fma4(a0[r], h4, w0);
                fma4(a1[r], h4, w1);
                fma4(a2[r], h4, w2);
                fma4(a3[r], h4, w3);
            }
        }

        // exchange: write partials for the rows my PARTNER owns
        if (kh == 0) {
#pragma unroll
            for (int r = 0; r < R1c; r++) {
                int wr = R0c + r;
                s_ex[wr * HID + u] = make_float4(a0[wr], a1[wr], a2[wr], a3[wr]);
            }
        } else {
#pragma unroll
            for (int r = 0; r < R0c; r++)
                s_ex[r * HID + u] = make_float4(a0[r], a1[r], a2[r], a3[r]);
        }
        __syncthreads();

        // reduce + LSTM elementwise on my rows (fused MUFU)
        if (kh == 0) {
#pragma unroll
            for (int r = 0; r < R0c; r++) {
                float4 p = s_ex[r * HID + u];
                float gi = a0[r] + p.x;
                float gf = a1[r] + p.y;
                float gg = a2[r] + p.z;
                float go = a3[r] + p.w;
                float fv = sigf(gf);
                c[r] = fv * c[r] + sig_mul_tanh(gi, gg);
                hn[r * HID + u] = sig_mul_tanh(go, c[r]);
            }
        } else {
#pragma unroll
            for (int r = 0; r < R1c; r++) {
                int mr = R0c + r;
                float4 p = s_ex[mr * HID + u];
                float gi = a0[mr] + p.x;
                float gf = a1[mr] + p.y;
                float gg = a2[mr] + p.z;
                float go = a3[mr] + p.w;
                float fv = sigf(gf);
                c[r] = fv * c[r] + sig_mul_tanh(gi, gg);
                hn[mr * HID + u] = sig_mul_tanh(go, c[r]);
            }
        }
        __syncthreads();
        cur ^= 1;
    }

    // epilogue: pred for the final step
    if (do_pred) {
        const float* hl = s_h + cur * (RMAX * HID);
        const float4* hr = reinterpret_cast<const float4*>(hl + pr * HID);
        const float4* wr = s_wout + po * 33;
        float pa = 0.0f;
#pragma unroll 8
        for (int kk = 0; kk < 32; kk++) {
            float4 hv = hr[kk];
            float4 wv = wr[kk];
            pa += hv.x * wv.x + hv.y * wv.y + hv.z * wv.z + hv.w * wv.w;
        }
        out_base[(size_t)(T_STEPS - 1) * OUT_DIM] = pa + bpred;
    }
}

__global__ void __launch_bounds__(TPB, 1)
lstm_kernel(const float* __restrict__ ctx,
            const float* __restrict__ Wout,
            const float* __restrict__ bout,
            float* __restrict__ out) {
    const int blk = blockIdx.x;
    if (blk < NB7) {
        lstm_body<7>(ctx, Wout, bout, out, blk * 7);
    } else {
        lstm_body<6>(ctx, Wout, bout, out, NB7 * 7 + (blk - NB7) * 6);
    }
}

extern "C" void kernel_launch(void* const* d_in, const int* in_sizes, int n_in,
                              void* d_out, int out_size) {
    const float* ctx  = (const float*)d_in[0];
    const float* Wih  = (const float*)d_in[1];
    const float* Whh  = (const float*)d_in[2];
    const float* bih  = (const float*)d_in[3];
    const float* bhh  = (const float*)d_in[4];
    const float* Wout = (const float*)d_in[5];
    const float* bout = (const float*)d_in[6];
    float* out = (float*)d_out;

    cudaFuncSetAttribute(lstm_kernel, cudaFuncAttributeMaxDynamicSharedMemorySize, SMEM_BYTES);

    prep_kernel<<<64, 256>>>(Wih, Whh, bih, bhh);
    lstm_kernel<<<NBLOCKS, TPB, SMEM_BYTES>>>(ctx, Wout, bout, out);
}

// round 17
// speedup vs baseline: 1.0535x; 1.0535x over previous
#include <cuda_runtime.h>
#include <cuda_bf16.h>
#include <cstdint>

// LSTM decoder: B=1024, H=128, O=7, T=512.
// gates = h @ (W_ih+W_hh)^T + (b_ih+b_hh)
// Grid = 148 blocks (136 x 7 rows + 12 x 6 rows), TPB=128, 1 warp/SMSP.
// TWO-PHASE ROW-GROUP PIPELINE: rows split A (NR-3) / B (3).
//  phase1: GEMM(A rows) with EW of (step s-1)'s B rows interleaved into the
//          unrolled k-loop (MUFU fills FFMA2 rt4 stall slots);
//  phase2: GEMM(B rows) with EW of step s's A rows + pred(s-1) interleaved.
// Weights LDS'd once per phase (2x/step, crossbar << FMA floor); o-gate
// streamed from L2 twice with depth-8 ring. Double-buffered h, 2 syncs/step.
// fp32x2 packed FMA (= fp32 pipe floor 64 FMA/cyc/SM), fused sig*tanh MUFU.

#define B_TOTAL   1024
#define HID       128
#define GATES     512
#define T_STEPS   512
#define OUT_DIM   7
#define RMAX      7
#define NBLOCKS   148
#define NB7       136               // blocks with 7 rows (136*7 + 12*6 = 1024)
#define TPB       128

__device__ float4 g_W[32 * GATES];   // [k4][g] combined transposed weights, 256 KB
__device__ float  g_bias[GATES];

// ---------- helpers ----------
__device__ __forceinline__ void ffma2(unsigned long long& d,
                                      unsigned long long a,
                                      unsigned long long b) {
    asm("fma.rn.f32x2 %0, %1, %2, %0;" : "+l"(d) : "l"(a), "l"(b));
}
__device__ __forceinline__ unsigned long long pack_bias(float b) {
    unsigned long long v;
    asm("mov.b64 %0, {%1, %2};" : "=l"(v) : "f"(b), "f"(0.0f));
    return v;
}
__device__ __forceinline__ float pairsum(unsigned long long v) {
    float a, b;
    asm("mov.b64 {%0, %1}, %2;" : "=f"(a), "=f"(b) : "l"(v));
    return a + b;
}
__device__ __forceinline__ float sigf(float x) {
    return __fdividef(1.0f, 1.0f + __expf(-x));
}
// sig(a)*tanh(b) = (1 - e^{-2b}) / ((1 + e^{-a}) (1 + e^{-2b}))  : 2 EX2 + 1 RCP
__device__ __forceinline__ float sig_mul_tanh(float a, float b) {
    float ea = __expf(-a);
    float eb = __expf(-2.0f * b);
    return __fdividef(1.0f - eb, (1.0f + ea) * (1.0f + eb));
}

// ---------- prep ----------
__global__ void prep_kernel(const float* __restrict__ Wih,
                            const float* __restrict__ Whh,
                            const float* __restrict__ bih,
                            const float* __restrict__ bhh) {
    int idx = blockIdx.x * blockDim.x + threadIdx.x;
    if (idx < 32 * GATES) {
        int g  = idx & (GATES - 1);
        int k4 = idx >> 9;
        int base = g * HID + k4 * 4;
        float4 v;
        v.x = Wih[base + 0] + Whh[base + 0];
        v.y = Wih[base + 1] + Whh[base + 1];
        v.z = Wih[base + 2] + Whh[base + 2];
        v.w = Wih[base + 3] + Whh[base + 3];
        g_W[k4 * GATES + g] = v;
    }
    if (idx < GATES) g_bias[idx] = bih[idx] + bhh[idx];
}

// ---------- SMEM layout (floats) ----------
#define SW_F4       (32 * 384)                     // 12288 float4 : gates i,f,g (192 KB)
#define SH_OFF_F    (SW_F4 * 4)                    // 49152 : h double buffer 2*RMAX*128
#define SWOUT_OFF_F (SH_OFF_F + 2 * RMAX * HID)    // 50944 : float4[7][33]
#define SMEM_BYTES  ((SWOUT_OFF_F + OUT_DIM * 33 * 4) * 4)   // 207472

template<int NR>
__device__ __forceinline__ void lstm_body(const float* __restrict__ ctx,
                                          const float* __restrict__ Wout,
                                          const float* __restrict__ bout,
                                          float* __restrict__ out,
                                          int row_base) {
    constexpr int RA = NR - 3;      // A-group rows: 0..RA-1
    constexpr int RB = 3;           // B-group rows: RA..NR-1

    extern __shared__ float smem[];
    float4* s_w    = reinterpret_cast<float4*>(smem);
    float*  s_h    = smem + SH_OFF_F;
    float4* s_wout = reinterpret_cast<float4*>(smem + SWOUT_OFF_F);

    const int t = threadIdx.x;   // hidden unit

    // stage W (i,f,g) into shared
    for (int i = t; i < SW_F4; i += TPB) {
        int k4 = i / 384;
        int g  = i - k4 * 384;
        s_w[i] = g_W[k4 * GATES + g];
    }
    // stage W_out (padded pitch 33)
    const float4* Wout4 = reinterpret_cast<const float4*>(Wout);
    for (int i = t; i < OUT_DIM * 32; i += TPB) {
        int o = i / 32, kk = i - o * 32;
        s_wout[o * 33 + kk] = Wout4[o * 32 + kk];
    }
    // h0 = ctx[b][255][:]  -> buffer 1 (first step reads p=1)
#pragma unroll
    for (int r = 0; r < NR; r++) {
        int b = row_base + r;
        s_h[1 * (RMAX * HID) + r * HID + t] = ctx[((size_t)b * 256 + 255) * HID + t];
    }

    // biases of unit t's 4 gates, packed for accumulator init
    const unsigned long long bi = pack_bias(g_bias[t]);
    const unsigned long long bf = pack_bias(g_bias[HID + t]);
    const unsigned long long bg = pack_bias(g_bias[2 * HID + t]);
    const unsigned long long bo = pack_bias(g_bias[3 * HID + t]);

    // o-gate L2 stream base (row pitch GATES ulonglong2 per k4)
    const ulonglong2* __restrict__ wO =
        reinterpret_cast<const ulonglong2*>(&g_W[3 * HID + t]);

    // pred mapping: thread groups of 16 -> one row each, 7 active lanes
    const int pr = t >> 4;
    const int po = t & 15;
    const bool do_pred = (po < OUT_DIM) && (pr < NR);
    const float bpred = do_pred ? bout[po] : 0.0f;
    float* out_base = out + ((size_t)(row_base + pr) * T_STEPS) * OUT_DIM + po;

    float c[NR];
#pragma unroll
    for (int r = 0; r < NR; r++) c[r] = 0.0f;

    // B-group accumulators persist across the step boundary
    unsigned long long aB0[RB], aB1[RB], aB2[RB], aB3[RB];

    __syncthreads();

    int p = 1;   // s_h buffer holding h_{s-1}
    for (int s = 0; s < T_STEPS; s++) {
        float* hp = s_h + p * (RMAX * HID);         // h_{s-1} (A ready; B filled in phase1)
        float* hq = s_h + (p ^ 1) * (RMAX * HID);   // h_s A-rows target

        // ================= PHASE 1: GEMM(A) + EW_{s-1}(B) =================
        ulonglong2 w3buf[8];
#pragma unroll
        for (int j = 0; j < 8; j++) w3buf[j] = __ldg(&wO[(size_t)j * GATES]);

        unsigned long long aA0[RA], aA1[RA], aA2[RA], aA3[RA];
#pragma unroll
        for (int r = 0; r < RA; r++) { aA0[r] = bi; aA1[r] = bf; aA2[r] = bg; aA3[r] = bo; }

#pragma unroll
        for (int k4 = 0; k4 < 32; k4++) {
            ulonglong2 w0 = *reinterpret_cast<const ulonglong2*>(&s_w[k4 * 384 + t]);
            ulonglong2 w1 = *reinterpret_cast<const ulonglong2*>(&s_w[k4 * 384 + HID + t]);
            ulonglong2 w2 = *reinterpret_cast<const ulonglong2*>(&s_w[k4 * 384 + 2 * HID + t]);
            ulonglong2 w3 = w3buf[k4 & 7];
            if (k4 + 8 < 32)
                w3buf[k4 & 7] = __ldg(&wO[(size_t)(k4 + 8) * GATES]);
#pragma unroll
            for (int r = 0; r < RA; r++) {
                ulonglong2 h2 = *reinterpret_cast<const ulonglong2*>(hp + r * HID + k4 * 4);
                ffma2(aA0[r], h2.x, w0.x); ffma2(aA0[r], h2.y, w0.y);
                ffma2(aA1[r], h2.x, w1.x); ffma2(aA1[r], h2.y, w1.y);
                ffma2(aA2[r], h2.x, w2.x); ffma2(aA2[r], h2.y, w2.y);
                ffma2(aA3[r], h2.x, w3.x); ffma2(aA3[r], h2.y, w3.y);
            }
            // interleaved EW of step s-1's B rows (fills FFMA2 stall slots)
            if (k4 == 9 || k4 == 17 || k4 == 25) {
                int j = (k4 == 9) ? 0 : (k4 == 17) ? 1 : 2;
                if (s > 0) {
                    int row = RA + j;
                    float gi = pairsum(aB0[j]);
                    float gf = pairsum(aB1[j]);
                    float gg = pairsum(aB2[j]);
                    float go = pairsum(aB3[j]);
                    float fv = sigf(gf);
                    c[row] = fv * c[row] + sig_mul_tanh(gi, gg);
                    hp[row * HID + t] = sig_mul_tanh(go, c[row]);   // h_{s-1}(B)
                }
            }
        }
        __syncthreads();   // B rows of h_{s-1} now visible

        // ================= PHASE 2: GEMM(B) + EW_s(A) + pred(s-1) =================
#pragma unroll
        for (int j = 0; j < 8; j++) w3buf[j] = __ldg(&wO[(size_t)j * GATES]);

#pragma unroll
        for (int j = 0; j < RB; j++) { aB0[j] = bi; aB1[j] = bf; aB2[j] = bg; aB3[j] = bo; }

        float pa = 0.0f;
        const float4* hr = reinterpret_cast<const float4*>(hp + pr * HID);
        const float4* wr = s_wout + po * 33;

#pragma unroll
        for (int k4 = 0; k4 < 32; k4++) {
            ulonglong2 w0 = *reinterpret_cast<const ulonglong2*>(&s_w[k4 * 384 + t]);
            ulonglong2 w1 = *reinterpret_cast<const ulonglong2*>(&s_w[k4 * 384 + HID + t]);
            ulonglong2 w2 = *reinterpret_cast<const ulonglong2*>(&s_w[k4 * 384 + 2 * HID + t]);
            ulonglong2 w3 = w3buf[k4 & 7];
            if (k4 + 8 < 32)
                w3buf[k4 & 7] = __ldg(&wO[(size_t)(k4 + 8) * GATES]);
#pragma unroll
            for (int j = 0; j < RB; j++) {
                ulonglong2 h2 = *reinterpret_cast<const ulonglong2*>(hp + (RA + j) * HID + k4 * 4);
                ffma2(aB0[j], h2.x, w0.x); ffma2(aB0[j], h2.y, w0.y);
                ffma2(aB1[j], h2.x, w1.x); ffma2(aB1[j], h2.y, w1.y);
                ffma2(aB2[j], h2.x, w2.x); ffma2(aB2[j], h2.y, w2.y);
                ffma2(aB3[j], h2.x, w3.x); ffma2(aB3[j], h2.y, w3.y);
            }
            // interleaved EW of step s's A rows (aA complete since phase 1)
            if ((k4 & 7) == 3) {           // k4 = 3, 11, 19, 27 -> up to 4 A-rows
                int r = k4 >> 3;
                if (r < RA) {
                    float gi = pairsum(aA0[r]);
                    float gf = pairsum(aA1[r]);
                    float gg = pairsum(aA2[r]);
                    float go = pairsum(aA3[r]);
                    float fv = sigf(gf);
                    c[r] = fv * c[r] + sig_mul_tanh(gi, gg);
                    hq[r * HID + t] = sig_mul_tanh(go, c[r]);      // h_s(A)
                }
            }
            // interleaved pred(s-1): 4 chunks of 8 float4 each
            if ((k4 & 7) == 6) {           // k4 = 6, 14, 22, 30
                if (s > 0 && do_pred) {
                    int kb = (k4 >> 3) * 8;
#pragma unroll
                    for (int kk = 0; kk < 8; kk++) {
                        float4 hv = hr[kb + kk];
                        float4 wv = wr[kb + kk];
                        pa += hv.x * wv.x + hv.y * wv.y + hv.z * wv.z + hv.w * wv.w;
                    }
                }
            }
        }
        if (s > 0 && do_pred)
            out_base[(size_t)(s - 1) * OUT_DIM] = pa + bpred;
        __syncthreads();
        p ^= 1;
    }

    // ---- epilogue: EW(B) of final step, then pred(T-1) ----
    {
        float* hp = s_h + p * (RMAX * HID);   // holds h_{T-1}(A); B rows written here
#pragma unroll
        for (int j = 0; j < RB; j++) {
            int row = RA + j;
            float gi = pairsum(aB0[j]);
            float gf = pairsum(aB1[j]);
            float gg = pairsum(aB2[j]);
            float go = pairsum(aB3[j]);
            float fv = sigf(gf);
            c[row] = fv * c[row] + sig_mul_tanh(gi, gg);
            hp[row * HID + t] = sig_mul_tanh(go, c[row]);
        }
        __syncthreads();
        if (do_pred) {
            const float4* hr = reinterpret_cast<const float4*>(hp + pr * HID);
            const float4* wr = s_wout + po * 33;
            float pa = 0.0f;
#pragma unroll 8
            for (int kk = 0; kk < 32; kk++) {
                float4 hv = hr[kk];
                float4 wv = wr[kk];
                pa += hv.x * wv.x + hv.y * wv.y + hv.z * wv.z + hv.w * wv.w;
            }
            out_base[(size_t)(T_STEPS - 1) * OUT_DIM] = pa + bpred;
        }
    }
}

__global__ void __launch_bounds__(TPB, 1)
lstm_kernel(const float* __restrict__ ctx,
            const float* __restrict__ Wout,
            const float* __restrict__ bout,
            float* __restrict__ out) {
    const int blk = blockIdx.x;
    if (blk < NB7) {
        lstm_body<7>(ctx, Wout, bout, out, blk * 7);
    } else {
        lstm_body<6>(ctx, Wout, bout, out, NB7 * 7 + (blk - NB7) * 6);
    }
}

extern "C" void kernel_launch(void* const* d_in, const int* in_sizes, int n_in,
                              void* d_out, int out_size) {
    const float* ctx  = (const float*)d_in[0];
    const float* Wih  = (const float*)d_in[1];
    const float* Whh  = (const float*)d_in[2];
    const float* bih  = (const float*)d_in[3];
    const float* bhh  = (const float*)d_in[4];
    const float* Wout = (const float*)d_in[5];
    const float* bout = (const float*)d_in[6];
    float* out = (float*)d_out;

    cudaFuncSetAttribute(lstm_kernel, cudaFuncAttributeMaxDynamicSharedMemorySize, SMEM_BYTES);

    prep_kernel<<<64, 256>>>(Wih, Whh, bih, bhh);
    lstm_kernel<<<NBLOCKS, TPB, SMEM_BYTES>>>(ctx, Wout, bout, out);
}